// round 6
// baseline (speedup 1.0000x reference)
#include <cuda_runtime.h>

#define NN   16384
#define EE   524288
#define DIN  256
#define DOUT 128
#define X_ELEMS (NN * DOUT)
#define A_F4   ((size_t)NN * (size_t)NN / 4)   // 67,108,864 float4 = 2^26

#define ZBLOCKS 512   // power of two: stride math divides A_F4 exactly

// Scratch (no allocations allowed).
__device__ float g_s[EE];      // per-edge exp(s)
__device__ float g_ssum[NN];   // per-row sum of exp(s)
__device__ int   g_cnt[NN];    // per-row edge count (degenerate-row fallback)
__device__ float g_sq[NN];     // per-row squared L2 norm of x

// Persistent co-resident zero of A. Low block count (≈3.5/SM) so it shares
// SMs with gemm/score; DRAM-store-bound, leaves exec pipes + warp slots free.
// stride = 512*256 = 2^17 float4; 4 stores/iter -> 2^19 per sweep;
// A_F4 = 2^26 -> exactly 128 iterations, no tail.
__global__ __launch_bounds__(256) void zero_kernel(float4* __restrict__ A4) {
    size_t t      = (size_t)blockIdx.x * 256 + threadIdx.x;
    const size_t stride = (size_t)ZBLOCKS * 256;
    float4 z = make_float4(0.f, 0.f, 0.f, 0.f);
    for (size_t i = t; i < A_F4; i += stride * 4) {
        __stcs(A4 + i,              z);
        __stcs(A4 + i + stride,     z);
        __stcs(A4 + i + stride * 2, z);
        __stcs(A4 + i + stride * 3, z);
    }
}

// x = In[16384,256] @ W[256,128]. Also zeroes ssum/cnt and computes per-row
// squared norms from register accumulators.
__global__ __launch_bounds__(256) void gemm_kernel(const float* __restrict__ In,
                                                   const float* __restrict__ W,
                                                   float* __restrict__ X) {
    if (threadIdx.x < 64) {
        int r = blockIdx.x * 64 + threadIdx.x;
        g_ssum[r] = 0.0f;
        g_cnt[r]  = 0;
    }

    __shared__ float As[64][32];
    __shared__ float Bs[32][128];
    __shared__ float ssq[64];
    const int tid  = threadIdx.x;
    const int brow = blockIdx.x * 64;
    const int tcol = (tid & 15) * 8;
    const int trow = (tid >> 4) * 4;
    if (tid < 64) ssq[tid] = 0.0f;

    float acc[4][8];
#pragma unroll
    for (int i = 0; i < 4; i++)
#pragma unroll
        for (int j = 0; j < 8; j++) acc[i][j] = 0.0f;

    for (int k0 = 0; k0 < DIN; k0 += 32) {
#pragma unroll
        for (int i = 0; i < 2; i++) {
            int idx = tid + i * 256;
            int r = idx >> 3;
            int c = (idx & 7) << 2;
            float4 v = *(const float4*)(In + (size_t)(brow + r) * DIN + k0 + c);
            *(float4*)&As[r][c] = v;
        }
#pragma unroll
        for (int i = 0; i < 4; i++) {
            int idx = tid + i * 256;
            int r = idx >> 5;
            int c = (idx & 31) << 2;
            float4 v = *(const float4*)(W + (size_t)(k0 + r) * DOUT + c);
            *(float4*)&Bs[r][c] = v;
        }
        __syncthreads();
#pragma unroll
        for (int k = 0; k < 32; k++) {
            float4 b0 = *(float4*)&Bs[k][tcol];
            float4 b1 = *(float4*)&Bs[k][tcol + 4];
            float b[8] = {b0.x, b0.y, b0.z, b0.w, b1.x, b1.y, b1.z, b1.w};
#pragma unroll
            for (int i = 0; i < 4; i++) {
                float av = As[trow + i][k];
#pragma unroll
                for (int j = 0; j < 8; j++) acc[i][j] = fmaf(av, b[j], acc[i][j]);
            }
        }
        __syncthreads();
    }
#pragma unroll
    for (int i = 0; i < 4; i++) {
        float4 o0 = {acc[i][0], acc[i][1], acc[i][2], acc[i][3]};
        float4 o1 = {acc[i][4], acc[i][5], acc[i][6], acc[i][7]};
        size_t base = (size_t)(brow + trow + i) * DOUT + tcol;
        *(float4*)(X + base)     = o0;
        *(float4*)(X + base + 4) = o1;
        float p = acc[i][0]*acc[i][0] + acc[i][1]*acc[i][1] + acc[i][2]*acc[i][2] + acc[i][3]*acc[i][3]
                + acc[i][4]*acc[i][4] + acc[i][5]*acc[i][5] + acc[i][6]*acc[i][6] + acc[i][7]*acc[i][7];
        atomicAdd(&ssq[trow + i], p);
    }
    __syncthreads();
    if (tid < 64) g_sq[brow + tid] = ssq[tid];
}

// Per-edge: ex = exp(dot(relu(xi*xj),a) * rsqrt(sq_i*sq_j)) if dot>0 else 0.
// s is bounded by ||a||_2 (~1.4) so exp cannot overflow; max-shift is
// mathematically redundant. One warp per edge. Gather-only (L2-bound),
// overlaps the concurrent DRAM-bound zero_kernel.
__global__ __launch_bounds__(256) void score_kernel(const float* __restrict__ X,
                                                    const int* __restrict__ edge,
                                                    const float* __restrict__ a) {
    int e    = (int)((blockIdx.x * 256u + threadIdx.x) >> 5);
    int lane = threadIdx.x & 31;
    if (e >= EE) return;
    int row = edge[e];
    int col = edge[EE + e];

    float4 xi = *(const float4*)(X + (size_t)row * DOUT + lane * 4);
    float4 xj = *(const float4*)(X + (size_t)col * DOUT + lane * 4);
    float4 av = *(const float4*)(a + lane * 4);

    float t = fmaxf(xi.x * xj.x, 0.0f) * av.x
            + fmaxf(xi.y * xj.y, 0.0f) * av.y
            + fmaxf(xi.z * xj.z, 0.0f) * av.z
            + fmaxf(xi.w * xj.w, 0.0f) * av.w;
#pragma unroll
    for (int o = 16; o; o >>= 1) t += __shfl_down_sync(0xffffffffu, t, o);

    if (lane == 0) {
        float ex = 0.0f;
        if (t > 0.0f) ex = __expf(t * rsqrtf(g_sq[row] * g_sq[col]));
        g_s[e] = ex;
        atomicAdd(&g_ssum[row], ex);
        atomicAdd(&g_cnt[row], 1);
    }
}

// vals = ex / ssum[row] (or 1/cnt for all-gated rows); scatter-add into A.
__global__ void scatter_kernel(const int* __restrict__ edge, float* __restrict__ A) {
    int e = blockIdx.x * blockDim.x + threadIdx.x;
    if (e >= EE) return;
    int row = edge[e];
    int col = edge[EE + e];
    float denom = g_ssum[row];
    float v = (denom > 0.0f) ? (g_s[e] / denom) : (1.0f / (float)g_cnt[row]);
    atomicAdd(A + (size_t)row * NN + col, v);
}

extern "C" void kernel_launch(void* const* d_in, const int* in_sizes, int n_in,
                              void* d_out, int out_size) {
    const float* In   = (const float*)d_in[0];   // [16384, 256]
    const int*   edge = (const int*)d_in[1];     // [2, 524288]
    const float* W    = (const float*)d_in[2];   // [256, 128]
    const float* a    = (const float*)d_in[3];   // [128, 1]
    float* X = (float*)d_out;                    // [16384, 128]
    float* A = X + X_ELEMS;                      // [16384, 16384]

    // Side branch: persistent co-resident zero of A, overlapping gemm+score.
    // Streams/events created fresh each call (deterministic) and intentionally
    // leaked (kernel_launch runs only for correctness + capture).
    cudaStream_t s2;
    cudaStreamCreateWithFlags(&s2, cudaStreamNonBlocking);
    cudaEvent_t evFork, evJoin;
    cudaEventCreateWithFlags(&evFork, cudaEventDisableTiming);
    cudaEventCreateWithFlags(&evJoin, cudaEventDisableTiming);

    cudaEventRecord(evFork, 0);
    cudaStreamWaitEvent(s2, evFork, 0);
    zero_kernel<<<ZBLOCKS, 256, 0, s2>>>((float4*)A);
    cudaEventRecord(evJoin, s2);

    gemm_kernel<<<NN / 64, 256>>>(In, W, X);
    score_kernel<<<EE / 8, 256>>>(X, edge, a);

    cudaStreamWaitEvent(0, evJoin, 0);
    scatter_kernel<<<EE / 256, 256>>>(edge, A);
}

// round 7
// speedup vs baseline: 1.1363x; 1.1363x over previous
#include <cuda_runtime.h>

#define NN   16384
#define EE   524288
#define DIN  256
#define DOUT 128
#define X_ELEMS (NN * DOUT)

// A = 67,108,864 float4 total.
// gemm: 512 blocks x 20480 f4 (320KB)  = 10,485,760 f4 (160MB)
// score: 65536 blocks x 864 f4 (13.5KB) = 56,623,104 f4 (906MB)
#define GEMM_Z_F4_PER_BLOCK   20480
#define SCORE_Z_F4_PER_BLOCK  864
#define SCORE_Z_OFF_F4        10485760

// Scratch (no allocations allowed).
__device__ float g_s[EE];      // per-edge exp(s)
__device__ float g_ssum[NN];   // per-row sum of exp(s)
__device__ int   g_cnt[NN];    // per-row edge count (degenerate-row fallback)
__device__ float g_sq[NN];     // per-row squared L2 norm of x

// x = In[16384,256] @ W[256,128]. 32-row tile, 512 blocks (fixes grid-limited
// occupancy seen at 64-row/256 blocks). Also zeroes a 320KB chunk of A with
// fire-and-forget streaming stores, zeroes ssum/cnt, computes per-row sq norms.
__global__ __launch_bounds__(256) void gemm_kernel(const float* __restrict__ In,
                                                   const float* __restrict__ W,
                                                   float* __restrict__ X,
                                                   float* __restrict__ A) {
    // async zero of A chunk (overlaps with compute below)
    {
        float4 z4 = make_float4(0.f, 0.f, 0.f, 0.f);
        float4* zdst = reinterpret_cast<float4*>(A)
                     + (size_t)blockIdx.x * GEMM_Z_F4_PER_BLOCK;
#pragma unroll 8
        for (int i = threadIdx.x; i < GEMM_Z_F4_PER_BLOCK; i += 256)
            __stcs(zdst + i, z4);
    }
    if (threadIdx.x < 32) {
        int r = blockIdx.x * 32 + threadIdx.x;
        g_ssum[r] = 0.0f;
        g_cnt[r]  = 0;
    }

    __shared__ float As[32][32];
    __shared__ float Bs[32][128];
    __shared__ float ssq[32];
    const int tid  = threadIdx.x;
    const int brow = blockIdx.x * 32;
    const int tcol = (tid & 15) * 8;   // 8 output cols
    const int trow = (tid >> 4) * 2;   // 2 output rows
    if (tid < 32) ssq[tid] = 0.0f;

    float acc[2][8];
#pragma unroll
    for (int i = 0; i < 2; i++)
#pragma unroll
        for (int j = 0; j < 8; j++) acc[i][j] = 0.0f;

    for (int k0 = 0; k0 < DIN; k0 += 32) {
        {   // As: 32x32 = 256 float4, 1 per thread
            int r = tid >> 3;
            int c = (tid & 7) << 2;
            float4 v = *(const float4*)(In + (size_t)(brow + r) * DIN + k0 + c);
            *(float4*)&As[r][c] = v;
        }
#pragma unroll
        for (int i = 0; i < 4; i++) {   // Bs: 32x128 = 1024 float4, 4 per thread
            int idx = tid + i * 256;
            int r = idx >> 5;
            int c = (idx & 31) << 2;
            float4 v = *(const float4*)(W + (size_t)(k0 + r) * DOUT + c);
            *(float4*)&Bs[r][c] = v;
        }
        __syncthreads();
#pragma unroll
        for (int k = 0; k < 32; k++) {
            float4 b0 = *(float4*)&Bs[k][tcol];
            float4 b1 = *(float4*)&Bs[k][tcol + 4];
            float b[8] = {b0.x, b0.y, b0.z, b0.w, b1.x, b1.y, b1.z, b1.w};
#pragma unroll
            for (int i = 0; i < 2; i++) {
                float av = As[trow + i][k];
#pragma unroll
                for (int j = 0; j < 8; j++) acc[i][j] = fmaf(av, b[j], acc[i][j]);
            }
        }
        __syncthreads();
    }
#pragma unroll
    for (int i = 0; i < 2; i++) {
        float4 o0 = {acc[i][0], acc[i][1], acc[i][2], acc[i][3]};
        float4 o1 = {acc[i][4], acc[i][5], acc[i][6], acc[i][7]};
        size_t base = (size_t)(brow + trow + i) * DOUT + tcol;
        *(float4*)(X + base)     = o0;
        *(float4*)(X + base + 4) = o1;
        float p = acc[i][0]*acc[i][0] + acc[i][1]*acc[i][1] + acc[i][2]*acc[i][2] + acc[i][3]*acc[i][3]
                + acc[i][4]*acc[i][4] + acc[i][5]*acc[i][5] + acc[i][6]*acc[i][6] + acc[i][7]*acc[i][7];
        atomicAdd(&ssq[trow + i], p);
    }
    __syncthreads();
    if (tid < 32) g_sq[brow + tid] = ssq[tid];
}

// Per-edge: ex = exp(dot(relu(xi*xj),a) * rsqrt(sq_i*sq_j)) if dot>0 else 0.
// s bounded by ||a||_2 (~1.4) => exp cannot overflow; max-shift redundant.
// One warp per edge. Also zeroes 13.5KB of A per block — stores overlap the
// L2-latency-bound gathers (proven in R2).
__global__ __launch_bounds__(256) void score_kernel(const float* __restrict__ X,
                                                    const int* __restrict__ edge,
                                                    const float* __restrict__ a,
                                                    float* __restrict__ A) {
    {
        float4 z4 = make_float4(0.f, 0.f, 0.f, 0.f);
        float4* zdst = reinterpret_cast<float4*>(A) + SCORE_Z_OFF_F4
                     + (size_t)blockIdx.x * SCORE_Z_F4_PER_BLOCK;
#pragma unroll
        for (int i = threadIdx.x; i < SCORE_Z_F4_PER_BLOCK; i += 256)
            __stcs(zdst + i, z4);
    }

    int e    = (int)((blockIdx.x * 256u + threadIdx.x) >> 5);
    int lane = threadIdx.x & 31;
    if (e >= EE) return;
    int row = edge[e];
    int col = edge[EE + e];

    float4 xi = *(const float4*)(X + (size_t)row * DOUT + lane * 4);
    float4 xj = *(const float4*)(X + (size_t)col * DOUT + lane * 4);
    float4 av = *(const float4*)(a + lane * 4);

    float t = fmaxf(xi.x * xj.x, 0.0f) * av.x
            + fmaxf(xi.y * xj.y, 0.0f) * av.y
            + fmaxf(xi.z * xj.z, 0.0f) * av.z
            + fmaxf(xi.w * xj.w, 0.0f) * av.w;
#pragma unroll
    for (int o = 16; o; o >>= 1) t += __shfl_down_sync(0xffffffffu, t, o);

    if (lane == 0) {
        float ex = 0.0f;
        if (t > 0.0f) ex = __expf(t * rsqrtf(g_sq[row] * g_sq[col]));
        g_s[e] = ex;
        atomicAdd(&g_ssum[row], ex);
        atomicAdd(&g_cnt[row], 1);
    }
}

// vals = ex / ssum[row] (or 1/cnt for all-gated rows); scatter-add into A.
__global__ void scatter_kernel(const int* __restrict__ edge, float* __restrict__ A) {
    int e = blockIdx.x * blockDim.x + threadIdx.x;
    if (e >= EE) return;
    int row = edge[e];
    int col = edge[EE + e];
    float denom = g_ssum[row];
    float v = (denom > 0.0f) ? (g_s[e] / denom) : (1.0f / (float)g_cnt[row]);
    atomicAdd(A + (size_t)row * NN + col, v);
}

extern "C" void kernel_launch(void* const* d_in, const int* in_sizes, int n_in,
                              void* d_out, int out_size) {
    const float* In   = (const float*)d_in[0];   // [16384, 256]
    const int*   edge = (const int*)d_in[1];     // [2, 524288]
    const float* W    = (const float*)d_in[2];   // [256, 128]
    const float* a    = (const float*)d_in[3];   // [128, 1]
    float* X = (float*)d_out;                    // [16384, 128]
    float* A = X + X_ELEMS;                      // [16384, 16384]

    gemm_kernel<<<NN / 32, 256>>>(In, W, X, A);
    score_kernel<<<EE / 8, 256>>>(X, edge, a, A);
    scatter_kernel<<<EE / 256, 256>>>(edge, A);
}

// round 8
// speedup vs baseline: 1.3650x; 1.2013x over previous
#include <cuda_runtime.h>

#define NN   16384
#define EE   524288
#define DIN  256
#define DOUT 128
#define X_ELEMS (NN * DOUT)

// score zeroes ALL of A: 65536 blocks x 1024 f4 = 67,108,864 f4 = 1073 MB.
#define SCORE_Z_F4_PER_BLOCK 1024

// Scratch (no allocations allowed).
__device__ float g_s[EE];      // per-edge exp(s)
__device__ float g_ssum[NN];   // per-row sum of exp(s)
__device__ int   g_cnt[NN];    // per-row edge count (degenerate-row fallback)
__device__ float g_sq[NN];     // per-row squared L2 norm of x

// x = In[16384,256] @ W[256,128]. 128x128 block tile, 8x8 register tile per
// thread (64 FMA per 4 LDS.128 -> FFMA-bound, not LDS-bound). No zero work.
// Also zeroes ssum/cnt and computes per-row squared norms.
__global__ __launch_bounds__(256) void gemm_kernel(const float* __restrict__ In,
                                                   const float* __restrict__ W,
                                                   float* __restrict__ X) {
    __shared__ float Ast[32][132];   // A tile, k-major transposed, padded
    __shared__ float Bs[32][128];    // B tile, k-major natural
    __shared__ float ssq[128];

    const int tid  = threadIdx.x;
    const int brow = blockIdx.x * 128;
    const int tx   = tid & 15;       // col group: cols tx*8 .. +7
    const int ty   = tid >> 4;       // row group: rows ty*8 .. +7

    if (tid < 128) {
        g_ssum[brow + tid] = 0.0f;
        g_cnt[brow + tid]  = 0;
        ssq[tid] = 0.0f;
    }

    float acc[8][8];
#pragma unroll
    for (int i = 0; i < 8; i++)
#pragma unroll
        for (int j = 0; j < 8; j++) acc[i][j] = 0.0f;

    for (int k0 = 0; k0 < DIN; k0 += 32) {
        // A tile: 128 rows x 32 k = 1024 f4, 4 per thread, stored transposed.
#pragma unroll
        for (int i = 0; i < 4; i++) {
            int f  = tid + i * 256;
            int r  = f >> 3;          // 0..127
            int c4 = f & 7;           // 0..7 (float4 index along k)
            float4 v = *(const float4*)(In + (size_t)(brow + r) * DIN + k0 + c4 * 4);
            Ast[c4 * 4 + 0][r] = v.x;
            Ast[c4 * 4 + 1][r] = v.y;
            Ast[c4 * 4 + 2][r] = v.z;
            Ast[c4 * 4 + 3][r] = v.w;
        }
        // B tile: 32 k x 128 cols = 1024 f4, 4 per thread.
#pragma unroll
        for (int i = 0; i < 4; i++) {
            int f = tid + i * 256;
            int r = f >> 5;           // 0..31
            int c = (f & 31) * 4;
            *(float4*)&Bs[r][c] = *(const float4*)(W + (size_t)(k0 + r) * DOUT + c);
        }
        __syncthreads();
#pragma unroll 4
        for (int k = 0; k < 32; k++) {
            float4 a0 = *(float4*)&Ast[k][ty * 8];
            float4 a1 = *(float4*)&Ast[k][ty * 8 + 4];
            float4 b0 = *(float4*)&Bs[k][tx * 8];
            float4 b1 = *(float4*)&Bs[k][tx * 8 + 4];
            float a[8] = {a0.x, a0.y, a0.z, a0.w, a1.x, a1.y, a1.z, a1.w};
            float b[8] = {b0.x, b0.y, b0.z, b0.w, b1.x, b1.y, b1.z, b1.w};
#pragma unroll
            for (int i = 0; i < 8; i++)
#pragma unroll
                for (int j = 0; j < 8; j++)
                    acc[i][j] = fmaf(a[i], b[j], acc[i][j]);
        }
        __syncthreads();
    }

#pragma unroll
    for (int i = 0; i < 8; i++) {
        int r = brow + ty * 8 + i;
        float4 o0 = {acc[i][0], acc[i][1], acc[i][2], acc[i][3]};
        float4 o1 = {acc[i][4], acc[i][5], acc[i][6], acc[i][7]};
        *(float4*)(X + (size_t)r * DOUT + tx * 8)     = o0;
        *(float4*)(X + (size_t)r * DOUT + tx * 8 + 4) = o1;
        float p = acc[i][0]*acc[i][0] + acc[i][1]*acc[i][1] + acc[i][2]*acc[i][2] + acc[i][3]*acc[i][3]
                + acc[i][4]*acc[i][4] + acc[i][5]*acc[i][5] + acc[i][6]*acc[i][6] + acc[i][7]*acc[i][7];
        atomicAdd(&ssq[ty * 8 + i], p);
    }
    __syncthreads();
    if (tid < 128) g_sq[brow + tid] = ssq[tid];
}

// Per-edge: ex = exp(dot(relu(xi*xj),a) * rsqrt(sq_i*sq_j)) if dot>0 else 0.
// s bounded by ||a||_2 (~1.4) => exp cannot overflow; max-shift redundant.
// One warp per edge. Zeroes 16KB of A per block (4 streaming stores/thread) —
// overlaps the L2-latency-bound gathers; kernel sits at the store floor.
__global__ __launch_bounds__(256) void score_kernel(const float* __restrict__ X,
                                                    const int* __restrict__ edge,
                                                    const float* __restrict__ a,
                                                    float* __restrict__ A) {
    {
        float4 z4 = make_float4(0.f, 0.f, 0.f, 0.f);
        float4* zdst = reinterpret_cast<float4*>(A)
                     + (size_t)blockIdx.x * SCORE_Z_F4_PER_BLOCK;
#pragma unroll
        for (int i = 0; i < 4; i++)
            __stcs(zdst + threadIdx.x + i * 256, z4);
    }

    int e    = (int)((blockIdx.x * 256u + threadIdx.x) >> 5);
    int lane = threadIdx.x & 31;
    if (e >= EE) return;
    int row = edge[e];
    int col = edge[EE + e];

    float4 xi = *(const float4*)(X + (size_t)row * DOUT + lane * 4);
    float4 xj = *(const float4*)(X + (size_t)col * DOUT + lane * 4);
    float4 av = *(const float4*)(a + lane * 4);

    float t = fmaxf(xi.x * xj.x, 0.0f) * av.x
            + fmaxf(xi.y * xj.y, 0.0f) * av.y
            + fmaxf(xi.z * xj.z, 0.0f) * av.z
            + fmaxf(xi.w * xj.w, 0.0f) * av.w;
#pragma unroll
    for (int o = 16; o; o >>= 1) t += __shfl_down_sync(0xffffffffu, t, o);

    if (lane == 0) {
        float ex = 0.0f;
        if (t > 0.0f) ex = __expf(t * rsqrtf(g_sq[row] * g_sq[col]));
        g_s[e] = ex;
        atomicAdd(&g_ssum[row], ex);
        atomicAdd(&g_cnt[row], 1);
    }
}

// vals = ex / ssum[row] (or 1/cnt for all-gated rows); scatter-add into A.
__global__ void scatter_kernel(const int* __restrict__ edge, float* __restrict__ A) {
    int e = blockIdx.x * blockDim.x + threadIdx.x;
    if (e >= EE) return;
    int row = edge[e];
    int col = edge[EE + e];
    float denom = g_ssum[row];
    float v = (denom > 0.0f) ? (g_s[e] / denom) : (1.0f / (float)g_cnt[row]);
    atomicAdd(A + (size_t)row * NN + col, v);
}

extern "C" void kernel_launch(void* const* d_in, const int* in_sizes, int n_in,
                              void* d_out, int out_size) {
    const float* In   = (const float*)d_in[0];   // [16384, 256]
    const int*   edge = (const int*)d_in[1];     // [2, 524288]
    const float* W    = (const float*)d_in[2];   // [256, 128]
    const float* a    = (const float*)d_in[3];   // [128, 1]
    float* X = (float*)d_out;                    // [16384, 128]
    float* A = X + X_ELEMS;                      // [16384, 16384]

    gemm_kernel<<<NN / 128, 256>>>(In, W, X);
    score_kernel<<<EE / 8, 256>>>(X, edge, a, A);
    scatter_kernel<<<EE / 256, 256>>>(edge, A);
}